// round 10
// baseline (speedup 1.0000x reference)
#include <cuda_runtime.h>
#include <cuda_fp16.h>
#include <cstdint>

#define NN 20000
#define CC 64
#define II 16
#define KK2 120
#define KK1 8
#define KK0 4

#define TPC 4
#define NS 10                 // k16 steps (K = 160)
#define QSTRIDE 88            // Q row stride in 32-bit words
#define SQW 11264             // Q region size in words
#define SFW 2560              // sF: 128 rows x 20 floats
#define SMEM_BYTES ((SQW + SFW) * 4)   // 55296

// device scratch
__device__ float    g_W2[CC * 4096];        // [c][x*256+y*16+i]
__device__ uint32_t g_VfragH[CC * 32 * 40]; // per-lane fp16x2 B fragments

// ---------------- helpers ----------------
struct PYI { int y, i; };
__host__ __device__ constexpr PYI pairOf(int p) {
    int y = 0, c = 16;
    while (p >= c) { p -= c; ++y; --c; }
    return {y, y + p};
}

__device__ __forceinline__ uint32_t packh2(float lo, float hi) {
    __half2 h = __floats2half2_rn(lo, hi);
    return *(uint32_t*)&h;
}
__device__ __forceinline__ void ldsv2(uint32_t& a, uint32_t& b, unsigned addr) {
    asm volatile("ld.shared.v2.b32 {%0,%1}, [%2];" : "=r"(a), "=r"(b) : "r"(addr));
}
__device__ __forceinline__ void mma16816(float (&d)[4], uint32_t a0, uint32_t a1,
                                         uint32_t a2, uint32_t a3, uint32_t b0,
                                         uint32_t b1) {
    asm volatile(
        "mma.sync.aligned.m16n8k16.row.col.f32.f16.f16.f32 "
        "{%0,%1,%2,%3},{%4,%5,%6,%7},{%8,%9},{%0,%1,%2,%3};"
        : "+f"(d[0]), "+f"(d[1]), "+f"(d[2]), "+f"(d[3])
        : "r"(a0), "r"(a1), "r"(a2), "r"(a3), "r"(b0), "r"(b1));
}

// feature value (plain k-index): 0=const, 1..16=f, 17..152=sym pairs, rest 0
template <int Q>
__device__ __forceinline__ float qv(const float (&f)[16]) {
    if constexpr (Q == 0) return 1.0f;
    else if constexpr (Q <= 16) return f[Q - 1];
    else if constexpr (Q < 153) {
        constexpr PYI pr = pairOf(Q - 17);
        return f[pr.y] * f[pr.i];
    } else return 0.0f;
}

// build 10 fp16 chunks for one row half (H warp-uniform).
// chunk (s,H): k-base B = 16s+4H, words = (B,B+1)(B+8,B+9)(B+2,B+3)(B+10,B+11)
template <int CH, int H>
__device__ __forceinline__ void buildQ(const float (&f)[16], unsigned wb) {
    if constexpr (CH < NS) {
        constexpr int B = 16 * CH + 4 * H;
        uint32_t w0 = packh2(qv<B + 0>(f),  qv<B + 1>(f));
        uint32_t w1 = packh2(qv<B + 8>(f),  qv<B + 9>(f));
        uint32_t w2 = packh2(qv<B + 2>(f),  qv<B + 3>(f));
        uint32_t w3 = packh2(qv<B + 10>(f), qv<B + 11>(f));
        asm volatile("st.shared.v4.b32 [%0], {%1,%2,%3,%4};"
                     :: "r"(wb + CH * 32), "r"(w0), "r"(w1), "r"(w2), "r"(w3)
                     : "memory");
        buildQ<CH + 1, H>(f, wb);
    }
}

// ---------------- precompute 1: W2 = U2 . w2 (grid 512, warp=row) ----------------
__global__ void __launch_bounds__(256) precompW2(const float* __restrict__ U2,
                                                 const float* __restrict__ w2) {
    __shared__ float sw[KK2 * CC];   // 30720 B
    __shared__ float su[8 * KK2];    // 3840 B
    int t = threadIdx.x;
    for (int j = t; j < KK2 * CC; j += 256) sw[j] = w2[j];
    int r0 = blockIdx.x * 8;
    for (int j = t; j < 8 * KK2; j += 256) su[j] = U2[(size_t)r0 * KK2 + j];
    __syncthreads();

    int w = t >> 5;      // warp = local row 0..7
    int lane = t & 31;   // 2 channels: 2*lane, 2*lane+1
    float a0 = 0.f, a1 = 0.f;
    const float* up = &su[w * KK2];
#pragma unroll 8
    for (int k = 0; k < KK2; k++) {
        float u = up[k];
        float2 wv = *(const float2*)&sw[k * CC + lane * 2];
        a0 = fmaf(u, wv.x, a0);
        a1 = fmaf(u, wv.y, a1);
    }
    int r = r0 + w;
    g_W2[(size_t)(lane * 2 + 0) * 4096 + r] = a0;
    g_W2[(size_t)(lane * 2 + 1) * 4096 + r] = a1;
}

// ---------------- precompute 2: per-lane fp16 B fragments (smem-tiled) ----------------
__device__ __forceinline__ float vvalS(int c, int x, int q, const float* sW,
                                       const float* U1, const float* w1,
                                       const float* U0, const float* w0) {
    float acc = 0.f;
    if (q == 0) {
#pragma unroll
        for (int k = 0; k < KK0; k++)
            acc = fmaf(U0[x * KK0 + k], w0[k * CC + c], acc);
    } else if (q <= 16) {
        int y = q - 1;
#pragma unroll
        for (int k = 0; k < KK1; k++)
            acc = fmaf(U1[(x * II + y) * KK1 + k], w1[k * CC + c], acc);
    } else if (q < 153) {
        int p = q - 17, y = 0, cnt = 16;
        while (p >= cnt) { p -= cnt; ++y; --cnt; }
        int i = y + p;
        acc = sW[x * 256 + y * 16 + i];
        if (i != y) acc += sW[x * 256 + i * 16 + y];
    }
    return acc;
}

__global__ void __launch_bounds__(256) precompVfrag(const float* __restrict__ U1,
                                                    const float* __restrict__ w1,
                                                    const float* __restrict__ U0,
                                                    const float* __restrict__ w0) {
    __shared__ float sW[4096];   // W2[c] tile, 16 KB
    int c = blockIdx.x;
    int t = threadIdx.x;
    for (int j = t; j < 4096; j += 256) sW[j] = g_W2[(size_t)c * 4096 + j];
    __syncthreads();

    for (int idx = t; idx < 1280; idx += 256) {
        int wq = idx & 3;
        int s = (idx >> 2) % NS;
        int lane = idx / 40;
        int g = lane >> 2, tg = lane & 3;
        int x = g + (wq >> 1) * 8;
        int kb = s * 16 + 2 * tg + (wq & 1) * 8;
        float vA = vvalS(c, x, kb,     sW, U1, w1, U0, w0);
        float vB = vvalS(c, x, kb + 1, sW, U1, w1, U0, w0);
        g_VfragH[(size_t)c * 1280 + idx] = packh2(vA, vB);
    }
}

// ---------------- main kernel ----------------
__global__ void __launch_bounds__(256, 3) contract_mma(const float* __restrict__ nf,
                                                       float* __restrict__ out) {
    extern __shared__ float sm[];
    float* sF = sm + SQW;
    unsigned sqb = (unsigned)__cvta_generic_to_shared(sm);
    int tid = threadIdx.x;
    int lane = tid & 31, w = tid >> 5;
    int g = lane >> 2, tg = lane & 3;
    int c = blockIdx.y;

    // B fragments: 10 x uint4 per lane, in registers for CTA lifetime
    uint4 bw[NS];
    const uint4* vp = (const uint4*)(g_VfragH + (size_t)(c * 32 + lane) * 40);
#pragma unroll
    for (int s = 0; s < NS; s++) bw[s] = vp[s];

    // loader mapping
    int la = tid >> 1, lh = tid & 1;
    // builder mapping (warp-uniform half)
    int ab = tid & 127, H = tid >> 7;
    unsigned wbq = sqb + (unsigned)(ab * QSTRIDE + ((ab >> 2) & 1) * 4 + H * 4) * 4;
    // MMA A addresses
    unsigned aA = sqb + (unsigned)((16 * w + g) * QSTRIDE + ((g >> 2) & 1) * 4
                                   + tg * 2) * 4;

    int tbase0 = blockIdx.x * TPC * 128;
    float4 pv0 = {0, 0, 0, 0}, pv1 = pv0;
    {
        int n = tbase0 + la;
        if (n < NN) {
            const float4* p = (const float4*)(nf + ((size_t)n * CC + c) * II + lh * 8);
            pv0 = p[0]; pv1 = p[1];
        }
    }

    for (int t = 0; t < TPC; t++) {
        int base = tbase0 + t * 128;
        if (base >= NN) break;

        // stage exact fp32 f
        *(float4*)&sF[la * 20 + lh * 8]     = pv0;
        *(float4*)&sF[la * 20 + lh * 8 + 4] = pv1;
        __syncthreads();

        // build fp16 Q (half row per thread, warp-uniform H)
        {
            float f[16];
            float4 c0 = *(float4*)&sF[ab * 20 + 0];
            float4 c1 = *(float4*)&sF[ab * 20 + 4];
            float4 c2 = *(float4*)&sF[ab * 20 + 8];
            float4 c3 = *(float4*)&sF[ab * 20 + 12];
            f[0] = c0.x; f[1] = c0.y; f[2] = c0.z; f[3] = c0.w;
            f[4] = c1.x; f[5] = c1.y; f[6] = c1.z; f[7] = c1.w;
            f[8] = c2.x; f[9] = c2.y; f[10] = c2.z; f[11] = c2.w;
            f[12] = c3.x; f[13] = c3.y; f[14] = c3.z; f[15] = c3.w;
            if (H == 0) buildQ<0, 0>(f, wbq);
            else        buildQ<0, 1>(f, wbq);
        }
        __syncthreads();

        // prefetch next tile's f
        pv0 = make_float4(0, 0, 0, 0); pv1 = pv0;
        if (t + 1 < TPC) {
            int n = base + 128 + la;
            if (n < NN) {
                const float4* p =
                    (const float4*)(nf + ((size_t)n * CC + c) * II + lh * 8);
                pv0 = p[0]; pv1 = p[1];
            }
        }

        // MMA: warp w handles rows 16w..16w+15
        float dA[4] = {0, 0, 0, 0}, dB[4] = {0, 0, 0, 0};
#pragma unroll
        for (int s = 0; s < NS; s++) {
            uint32_t a0, a2, a1, a3;
            ldsv2(a0, a2, aA + s * 32);
            ldsv2(a1, a3, aA + s * 32 + 8 * QSTRIDE * 4);
            mma16816(dA, a0, a1, a2, a3, bw[s].x, bw[s].y);
            mma16816(dB, a0, a1, a2, a3, bw[s].z, bw[s].w);
        }

        // epilogue: out = sum_x t[x] * f[x] (exact fp32 f)
#pragma unroll
        for (int h = 0; h < 2; h++) {
            int r = 16 * w + g + h * 8;
            float2 fa = *(const float2*)&sF[r * 20 + 2 * tg];
            float2 fb = *(const float2*)&sF[r * 20 + 8 + 2 * tg];
            float p = dA[h * 2] * fa.x + dA[h * 2 + 1] * fa.y
                    + dB[h * 2] * fb.x + dB[h * 2 + 1] * fb.y;
            p += __shfl_xor_sync(0xffffffffu, p, 1);
            p += __shfl_xor_sync(0xffffffffu, p, 2);
            int atom = base + r;
            if (tg == 0 && atom < NN) out[(size_t)atom * CC + c] = p;
        }
        __syncthreads();
    }
}

extern "C" void kernel_launch(void* const* d_in, const int* in_sizes, int n_in,
                              void* d_out, int out_size) {
    const float* nf = (const float*)d_in[0];
    const float* U2 = (const float*)d_in[1];
    const float* U1 = (const float*)d_in[2];
    const float* U0 = (const float*)d_in[3];
    const float* w2 = (const float*)d_in[4];
    const float* w1 = (const float*)d_in[5];
    const float* w0 = (const float*)d_in[6];
    float* out = (float*)d_out;

    cudaFuncSetAttribute(contract_mma, cudaFuncAttributeMaxDynamicSharedMemorySize,
                         SMEM_BYTES);

    precompW2<<<512, 256>>>(U2, w2);
    precompVfrag<<<CC, 256>>>(U1, w1, U0, w0);

    dim3 grid(40, CC);
    contract_mma<<<grid, 256, SMEM_BYTES>>>(nf, out);
}